// round 9
// baseline (speedup 1.0000x reference)
#include <cuda_runtime.h>

#define BB 512
#define KK 800
#define DD 512
#define LL 500000
#define NB 24
#define BSZ ((LL + NB - 1) / NB)     // 20834
#define NCELL (BB * NB)              // 12288 cells; cell c -> b = c & 511, bucket = c >> 9
#define GRID 1184                    // 8 blocks/SM on 148 SMs; ticket makes SM count irrelevant

// Work-stealing ticket. Zero at module load; self-reset by the block that draws
// the last overflow ticket, so every graph replay starts from 0.
__device__ int g_ticket;

__global__ __launch_bounds__(256, 8) void fused_kernel(
    const float* __restrict__ embed,
    const int*   __restrict__ shortlist,
    const float* __restrict__ sp_weight,
    const float* __restrict__ sp_bias,
    float*       __restrict__ out)
{
    __shared__ float4       s_embed[2][DD / 4];   // 4 KB  (double-buffered)
    __shared__ int4         s_sl[2][KK / 4];      // 6.4 KB (double-buffered raw shortlist)
    __shared__ unsigned int s_list[KK];           // 3.2 KB (filtered items, single)
    __shared__ int          s_cnt;
    __shared__ int          s_next;

    const int t    = threadIdx.x;
    const int lane = t & 31;
    const int warp = t >> 5;

    // ---- draw first cell & prefetch it into buffer 0 ----
    if (t == 0) s_next = atomicAdd(&g_ticket, 1);
    __syncthreads();
    int cur = s_next;

    if (cur < NCELL) {
        const int b = cur & (BB - 1);
        if (t < DD / 4) {
            unsigned dst = (unsigned)__cvta_generic_to_shared(&s_embed[0][t]);
            const float4* src = reinterpret_cast<const float4*>(embed + (size_t)b * DD) + t;
            asm volatile("cp.async.cg.shared.global [%0], [%1], 16;" :: "r"(dst), "l"(src));
        }
        if (t < KK / 4) {
            unsigned dst = (unsigned)__cvta_generic_to_shared(&s_sl[0][t]);
            const int4* src = reinterpret_cast<const int4*>(shortlist + (size_t)b * KK) + t;
            asm volatile("cp.async.cg.shared.global [%0], [%1], 16;" :: "r"(dst), "l"(src));
        }
    }
    asm volatile("cp.async.commit_group;");

    int buf = 0;
    while (cur < NCELL) {
        // ---- draw next cell; prefetch it into the other buffer ----
        if (t == 0) s_next = atomicAdd(&g_ticket, 1);
        __syncthreads();                       // (A) s_next visible; prev cell's s_list readers done
        const int nxt = s_next;

        if (nxt < NCELL) {
            const int nb_ = nxt & (BB - 1);
            const int pb  = buf ^ 1;
            if (t < DD / 4) {
                unsigned dst = (unsigned)__cvta_generic_to_shared(&s_embed[pb][t]);
                const float4* src = reinterpret_cast<const float4*>(embed + (size_t)nb_ * DD) + t;
                asm volatile("cp.async.cg.shared.global [%0], [%1], 16;" :: "r"(dst), "l"(src));
            }
            if (t < KK / 4) {
                unsigned dst = (unsigned)__cvta_generic_to_shared(&s_sl[pb][t]);
                const int4* src = reinterpret_cast<const int4*>(shortlist + (size_t)nb_ * KK) + t;
                asm volatile("cp.async.cg.shared.global [%0], [%1], 16;" :: "r"(dst), "l"(src));
            }
        }
        asm volatile("cp.async.commit_group;");
        asm volatile("cp.async.wait_group 1;"); // current buffer's group complete

        if (t == 0) s_cnt = 0;
        __syncthreads();                       // (B) buffer + s_cnt visible

        // ---- filter this bucket's items from the staged shortlist row ----
        const int b      = cur & (BB - 1);
        const int bucket = cur >> 9;
        const int lo = bucket * BSZ;
        const int hi = lo + BSZ;

        int4 v = make_int4(-1, -1, -1, -1);
        if (t < KK / 4) v = s_sl[buf][t];

        #pragma unroll
        for (int c = 0; c < 4; ++c) {
            int idx = (c == 0) ? v.x : (c == 1) ? v.y : (c == 2) ? v.z : v.w;
            bool m = (t < KK / 4) && (idx >= lo) && (idx < hi);
            unsigned bal = __ballot_sync(0xffffffffu, m);
            if (bal) {
                int base = 0;
                if (lane == 0) base = atomicAdd(&s_cnt, __popc(bal));
                base = __shfl_sync(0xffffffffu, base, 0);
                if (m) {
                    int off = __popc(bal & ((1u << lane) - 1u));
                    int k = t * 4 + c;
                    s_list[base + off] = ((unsigned)idx << 10) | (unsigned)k;
                }
            }
        }
        __syncthreads();                       // (C) s_list ready

        // ---- warp per item: float4-coalesced weight-row dot ----
        const int cnt = s_cnt;
        for (int j = warp; j < cnt; j += 8) {
            const unsigned int it  = s_list[j];
            const int          k   = (int)(it & 1023u);
            const long long    idx = (long long)(it >> 10);

            const float4* wrow =
                reinterpret_cast<const float4*>(sp_weight + idx * DD);

            float sum = 0.0f;
            #pragma unroll
            for (int i = 0; i < DD / 128; ++i) {   // 4 independent LDG.128
                float4 w = wrow[i * 32 + lane];
                float4 e = s_embed[buf][i * 32 + lane];
                sum = fmaf(w.x, e.x, sum);
                sum = fmaf(w.y, e.y, sum);
                sum = fmaf(w.z, e.z, sum);
                sum = fmaf(w.w, e.w, sum);
            }

            #pragma unroll
            for (int off = 16; off; off >>= 1)
                sum += __shfl_xor_sync(0xffffffffu, sum, off);

            if (lane == 0)
                out[b * KK + k] = sum + __ldg(&sp_bias[idx]);
        }

        cur = nxt;
        buf ^= 1;
    }

    // Exactly one block draws the final overflow ticket; it restores the
    // counter so the next (graph-replayed) launch starts from 0.
    if (t == 0 && cur == NCELL + GRID - 1)
        g_ticket = 0;
}

extern "C" void kernel_launch(void* const* d_in, const int* in_sizes, int n_in,
                              void* d_out, int out_size) {
    const float* embed     = (const float*)d_in[0];
    const int*   shortlist = (const int*)  d_in[1];
    const float* sp_weight = (const float*)d_in[2];
    const float* sp_bias   = (const float*)d_in[3];
    float*       out       = (float*)d_out;

    fused_kernel<<<GRID, 256>>>(embed, shortlist, sp_weight, sp_bias, out);
}